// round 1
// baseline (speedup 1.0000x reference)
#include <cuda_runtime.h>
#include <math.h>

// ---------------------------------------------------------------------------
// HeteroGAT encoder, fp32 baseline.
//   - 6 dense GEMMs (2 input proj + 4 per-layer src transforms)
//   - dst-side attention scores via skinny projected-weight GEMMs (no hd GEMM)
//   - CSR-by-dst built once per direction; fused per-dst softmax+aggregate
//   - fused LN + bias + relu + residual
// ---------------------------------------------------------------------------

#define NMAX 50000
#define EMAX 500000

// scratch (static __device__ — no allocations allowed)
__device__ float g_hA[NMAX * 128];
__device__ float g_hB[NMAX * 128];
__device__ float g_nA[NMAX * 128];
__device__ float g_nB[NMAX * 128];
__device__ float g_t1[NMAX * 128];
__device__ float g_t2[NMAX * 128];
__device__ float g_as1[NMAX * 4], g_ad1[NMAX * 4];
__device__ float g_as2[NMAX * 4], g_ad2[NMAX * 4];
__device__ float g_wpS1[128 * 4], g_wpD1[128 * 4];
__device__ float g_wpS2[128 * 4], g_wpD2[128 * 4];
__device__ int g_rpAB[NMAX + 1], g_rpBA[NMAX + 1];
__device__ int g_cur[NMAX], g_deg[NMAX];
__device__ int g_srcAB[EMAX], g_srcBA[EMAX];

// ---------------------------------------------------------------------------
// warp reduce helpers
// ---------------------------------------------------------------------------
__device__ __forceinline__ float warpSum(float v) {
#pragma unroll
    for (int o = 16; o > 0; o >>= 1) v += __shfl_xor_sync(0xffffffffu, v, o);
    return v;
}
__device__ __forceinline__ float warpMax(float v) {
#pragma unroll
    for (int o = 16; o > 0; o >>= 1) v = fmaxf(v, __shfl_xor_sync(0xffffffffu, v, o));
    return v;
}

// ---------------------------------------------------------------------------
// GEMM: out[M,128] = X[M,K] @ W[K,128] (+ bias). K in {64,128}.
// BM=64 rows/block, 256 threads, each thread: 8 rows x 4 cols.
// ---------------------------------------------------------------------------
__global__ __launch_bounds__(256) void gemm_bias_128(
    const float* __restrict__ X, const float* __restrict__ W,
    const float* __restrict__ bias, float* __restrict__ out, int M, int K) {
    __shared__ float Xs[64][33];   // +1 pad (column reads are broadcast anyway)
    __shared__ float Ws[32][128];

    const int block_row = blockIdx.x * 64;
    const int tid = threadIdx.x;
    const int tx = tid & 31;   // col group: cols tx*4 .. tx*4+3
    const int ty = tid >> 5;   // row group: rows ty*8 .. ty*8+7

    float acc[8][4];
#pragma unroll
    for (int i = 0; i < 8; i++)
#pragma unroll
        for (int j = 0; j < 4; j++) acc[i][j] = 0.f;

    for (int k0 = 0; k0 < K; k0 += 32) {
        // load X tile 64x32 (coalesced along k)
#pragma unroll
        for (int i = tid; i < 64 * 32; i += 256) {
            int r = i >> 5, c = i & 31;
            int gr = block_row + r;
            Xs[r][c] = (gr < M) ? X[(size_t)gr * K + k0 + c] : 0.f;
        }
        // load W tile 32x128 (coalesced along n)
#pragma unroll
        for (int i = tid; i < 32 * 128; i += 256) {
            int r = i >> 7, c = i & 127;
            Ws[r][c] = W[(size_t)(k0 + r) * 128 + c];
        }
        __syncthreads();
#pragma unroll
        for (int kk = 0; kk < 32; kk++) {
            float4 bv = *(const float4*)&Ws[kk][tx * 4];
#pragma unroll
            for (int i = 0; i < 8; i++) {
                float a = Xs[ty * 8 + i][kk];
                acc[i][0] += a * bv.x;
                acc[i][1] += a * bv.y;
                acc[i][2] += a * bv.z;
                acc[i][3] += a * bv.w;
            }
        }
        __syncthreads();
    }

    float4 bb = make_float4(0.f, 0.f, 0.f, 0.f);
    if (bias) bb = *(const float4*)&bias[tx * 4];
#pragma unroll
    for (int i = 0; i < 8; i++) {
        int gr = block_row + ty * 8 + i;
        if (gr < M) {
            float4 o;
            o.x = acc[i][0] + bb.x;
            o.y = acc[i][1] + bb.y;
            o.z = acc[i][2] + bb.z;
            o.w = acc[i][3] + bb.w;
            *(float4*)&out[(size_t)gr * 128 + tx * 4] = o;
        }
    }
}

// ---------------------------------------------------------------------------
// wp[k,h] = sum_d W[k, h*D+d] * a[h*D+d]  (projected attention weights)
// one block of 128 threads; computes both src and dst projections
// ---------------------------------------------------------------------------
template <int H>
__global__ void make_wp(const float* __restrict__ W, const float* __restrict__ avs,
                        const float* __restrict__ avd, float* __restrict__ wpS,
                        float* __restrict__ wpD) {
    const int D = 128 / H;
    int k = threadIdx.x;
#pragma unroll
    for (int h = 0; h < H; h++) {
        float ss = 0.f, sd = 0.f;
        for (int d = 0; d < D; d++) {
            float w = W[(size_t)k * 128 + h * D + d];
            ss += w * avs[h * D + d];
            sd += w * avd[h * D + d];
        }
        wpS[k * H + h] = ss;
        wpD[k * H + h] = sd;
    }
}

// ---------------------------------------------------------------------------
// node scores: out[n,h] = X[n,:] @ wp[:,h]   (warp per node)
// ---------------------------------------------------------------------------
template <int H>
__global__ void node_scores(const float* __restrict__ X, const float* __restrict__ wp,
                            float* __restrict__ out, int N) {
    int w = (blockIdx.x * blockDim.x + threadIdx.x) >> 5;
    int lane = threadIdx.x & 31;
    if (w >= N) return;
    const float* xr = X + (size_t)w * 128;
    float acc[H];
#pragma unroll
    for (int h = 0; h < H; h++) acc[h] = 0.f;
#pragma unroll
    for (int kk = 0; kk < 4; kk++) {
        int k = lane + kk * 32;
        float x = xr[k];
#pragma unroll
        for (int h = 0; h < H; h++) acc[h] += x * wp[k * H + h];
    }
#pragma unroll
    for (int h = 0; h < H; h++) acc[h] = warpSum(acc[h]);
    if (lane == 0) {
#pragma unroll
        for (int h = 0; h < H; h++) out[w * H + h] = acc[h];
    }
}

// ---------------------------------------------------------------------------
// CSR build
// ---------------------------------------------------------------------------
__global__ void edge_hist(const int* __restrict__ dst, int* __restrict__ deg, int E) {
    int e = blockIdx.x * blockDim.x + threadIdx.x;
    if (e < E) atomicAdd(&deg[dst[e]], 1);
}
__global__ void edge_fill(const int* __restrict__ src, const int* __restrict__ dst,
                          int* __restrict__ cursor, int* __restrict__ col, int E) {
    int e = blockIdx.x * blockDim.x + threadIdx.x;
    if (e < E) {
        int p = atomicAdd(&cursor[dst[e]], 1);
        col[p] = src[e];
    }
}
// single-block exclusive scan of deg[0..N) -> rowptr & cursor
__global__ void exscan_block(const int* __restrict__ deg, int* __restrict__ rowptr,
                             int* __restrict__ cursor, int N) {
    __shared__ int sums[256];
    int t = threadIdx.x;
    int chunk = (N + 255) / 256;
    int b0 = t * chunk;
    int b1 = min(b0 + chunk, N);
    int s = 0;
    for (int i = b0; i < b1; i++) s += deg[i];
    sums[t] = s;
    __syncthreads();
    for (int off = 1; off < 256; off <<= 1) {
        int v = (t >= off) ? sums[t - off] : 0;
        __syncthreads();
        sums[t] += v;
        __syncthreads();
    }
    int run = (t == 0) ? 0 : sums[t - 1];
    for (int i = b0; i < b1; i++) {
        rowptr[i] = run;
        cursor[i] = run;
        run += deg[i];
    }
    if (t == 255) rowptr[N] = run;
}

// ---------------------------------------------------------------------------
// fused GAT aggregation: warp per destination node.
//   phase A: segment max of leaky_relu(a_s[src]+a_d[dst]) per head
//   phase B: segment sum of exp(e - max)
//   phase C: out[dst,:] = sum_e alpha_e * tS[src_e,:]
// ---------------------------------------------------------------------------
template <int H>
__global__ void gat_aggregate(const int* __restrict__ rowptr, const int* __restrict__ srcs,
                              const float* __restrict__ a_s, const float* __restrict__ a_d,
                              const float* __restrict__ tS, float* __restrict__ outp,
                              int Ndst) {
    const int D = 128 / H;
    int wid = (blockIdx.x * blockDim.x + threadIdx.x) >> 5;
    int lane = threadIdx.x & 31;
    if (wid >= Ndst) return;
    int start = rowptr[wid];
    int end = rowptr[wid + 1];

    float adh[H];
#pragma unroll
    for (int h = 0; h < H; h++) adh[h] = a_d[wid * H + h];

    float mx[H];
#pragma unroll
    for (int h = 0; h < H; h++) mx[h] = -3.0e38f;
    for (int e = start + lane; e < end; e += 32) {
        int s = srcs[e];
#pragma unroll
        for (int h = 0; h < H; h++) {
            float sc = a_s[s * H + h] + adh[h];
            sc = sc > 0.f ? sc : 0.2f * sc;
            mx[h] = fmaxf(mx[h], sc);
        }
    }
#pragma unroll
    for (int h = 0; h < H; h++) mx[h] = warpMax(mx[h]);

    float sm[H];
#pragma unroll
    for (int h = 0; h < H; h++) sm[h] = 0.f;
    for (int e = start + lane; e < end; e += 32) {
        int s = srcs[e];
#pragma unroll
        for (int h = 0; h < H; h++) {
            float sc = a_s[s * H + h] + adh[h];
            sc = sc > 0.f ? sc : 0.2f * sc;
            sm[h] += __expf(sc - mx[h]);
        }
    }
#pragma unroll
    for (int h = 0; h < H; h++) sm[h] = warpSum(sm[h]);
    float inv[H];
#pragma unroll
    for (int h = 0; h < H; h++) inv[h] = 1.f / (sm[h] + 1e-16f);

    const int hh = (lane * 4) / D;  // head for this lane's 4 channels
    float4 acc = make_float4(0.f, 0.f, 0.f, 0.f);
    for (int e = start; e < end; e++) {
        int s = srcs[e];
        float sc = a_s[s * H + hh] + adh[hh];
        sc = sc > 0.f ? sc : 0.2f * sc;
        float alpha = __expf(sc - mx[hh]) * inv[hh];
        float4 v = *(const float4*)(tS + (size_t)s * 128 + lane * 4);
        acc.x += v.x * alpha;
        acc.y += v.y * alpha;
        acc.z += v.z * alpha;
        acc.w += v.w * alpha;
    }
    *(float4*)(outp + (size_t)wid * 128 + lane * 4) = acc;
}

// ---------------------------------------------------------------------------
// fused: h_out = relu(LN(n + bias) * g + b) + h_prev    (warp per node)
// ---------------------------------------------------------------------------
__global__ void ln_relu_residual(const float* __restrict__ nbuf, const float* __restrict__ bias,
                                 const float* __restrict__ gamma, const float* __restrict__ beta,
                                 const float* __restrict__ hprev, float* __restrict__ hout,
                                 int N) {
    int wid = (blockIdx.x * blockDim.x + threadIdx.x) >> 5;
    int lane = threadIdx.x & 31;
    if (wid >= N) return;
    size_t base = (size_t)wid * 128 + lane * 4;
    float4 v = *(const float4*)(nbuf + base);
    float4 bb = *(const float4*)(bias + lane * 4);
    v.x += bb.x; v.y += bb.y; v.z += bb.z; v.w += bb.w;
    float mu = warpSum(v.x + v.y + v.z + v.w) * (1.f / 128.f);
    float dx = v.x - mu, dy = v.y - mu, dz = v.z - mu, dw = v.w - mu;
    float var = warpSum(dx * dx + dy * dy + dz * dz + dw * dw) * (1.f / 128.f);
    float r = rsqrtf(var + 1e-5f);
    float4 g = *(const float4*)(gamma + lane * 4);
    float4 b = *(const float4*)(beta + lane * 4);
    float4 hp = *(const float4*)(hprev + base);
    float4 o;
    o.x = fmaxf(0.f, dx * r * g.x + b.x) + hp.x;
    o.y = fmaxf(0.f, dy * r * g.y + b.y) + hp.y;
    o.z = fmaxf(0.f, dz * r * g.z + b.z) + hp.z;
    o.w = fmaxf(0.f, dw * r * g.w + b.w) + hp.w;
    *(float4*)(hout + base) = o;
}

// ---------------------------------------------------------------------------
// host orchestration
// ---------------------------------------------------------------------------
static inline void* sym(const void* s) {
    void* p = nullptr;
    cudaGetSymbolAddress(&p, s);
    return p;
}

extern "C" void kernel_launch(void* const* d_in, const int* in_sizes, int n_in,
                              void* d_out, int out_size) {
    const float* x_A = (const float*)d_in[0];
    const float* x_B = (const float*)d_in[1];
    const float* pWA = (const float*)d_in[2];
    const float* pbA = (const float*)d_in[3];
    const float* pWB = (const float*)d_in[4];
    const float* pbB = (const float*)d_in[5];
    const float* w0ab = (const float*)d_in[6];
    const float* as0ab = (const float*)d_in[7];
    const float* ad0ab = (const float*)d_in[8];
    const float* b0ab = (const float*)d_in[9];
    const float* w0ba = (const float*)d_in[10];
    const float* as0ba = (const float*)d_in[11];
    const float* ad0ba = (const float*)d_in[12];
    const float* b0ba = (const float*)d_in[13];
    const float* w1ab = (const float*)d_in[14];
    const float* as1ab = (const float*)d_in[15];
    const float* ad1ab = (const float*)d_in[16];
    const float* b1ab = (const float*)d_in[17];
    const float* w1ba = (const float*)d_in[18];
    const float* as1ba = (const float*)d_in[19];
    const float* ad1ba = (const float*)d_in[20];
    const float* b1ba = (const float*)d_in[21];
    const float* g0A = (const float*)d_in[22];
    const float* bn0A = (const float*)d_in[23];
    const float* g0B = (const float*)d_in[24];
    const float* bn0B = (const float*)d_in[25];
    const float* g1A = (const float*)d_in[26];
    const float* bn1A = (const float*)d_in[27];
    const float* g1B = (const float*)d_in[28];
    const float* bn1B = (const float*)d_in[29];
    const int* ei_AB = (const int*)d_in[30];
    const int* ei_BA = (const int*)d_in[31];

    const int NA = in_sizes[0] / 128;
    const int NB = in_sizes[1] / 64;
    const int E = in_sizes[30] / 2;

    float* hA = (float*)sym(g_hA);
    float* hB = (float*)sym(g_hB);
    float* nA = (float*)sym(g_nA);
    float* nB = (float*)sym(g_nB);
    float* t1 = (float*)sym(g_t1);
    float* t2 = (float*)sym(g_t2);
    float* as1 = (float*)sym(g_as1);
    float* ad1 = (float*)sym(g_ad1);
    float* as2 = (float*)sym(g_as2);
    float* ad2 = (float*)sym(g_ad2);
    float* wpS1 = (float*)sym(g_wpS1);
    float* wpD1 = (float*)sym(g_wpD1);
    float* wpS2 = (float*)sym(g_wpS2);
    float* wpD2 = (float*)sym(g_wpD2);
    int* rpAB = (int*)sym(g_rpAB);
    int* rpBA = (int*)sym(g_rpBA);
    int* cur = (int*)sym(g_cur);
    int* deg = (int*)sym(g_deg);
    int* srcAB = (int*)sym(g_srcAB);
    int* srcBA = (int*)sym(g_srcBA);

    const int TB = 256;
    const int eb = (E + TB - 1) / TB;
    const int wbA = (NA * 32 + TB - 1) / TB;  // warp-per-node grids
    const int wbB = (NB * 32 + TB - 1) / TB;
    const int gbA = (NA + 63) / 64;
    const int gbB = (NB + 63) / 64;

    // --- CSR by destination, both directions (reused by both layers) ---
    cudaMemsetAsync(deg, 0, NB * sizeof(int));
    edge_hist<<<eb, TB>>>(ei_AB + E, deg, E);
    exscan_block<<<1, 256>>>(deg, rpAB, cur, NB);
    edge_fill<<<eb, TB>>>(ei_AB, ei_AB + E, cur, srcAB, E);

    cudaMemsetAsync(deg, 0, NA * sizeof(int));
    edge_hist<<<eb, TB>>>(ei_BA + E, deg, E);
    exscan_block<<<1, 256>>>(deg, rpBA, cur, NA);
    edge_fill<<<eb, TB>>>(ei_BA, ei_BA + E, cur, srcBA, E);

    // --- input projections ---
    gemm_bias_128<<<gbA, TB>>>(x_A, pWA, pbA, hA, NA, 128);
    gemm_bias_128<<<gbB, TB>>>(x_B, pWB, pbB, hB, NB, 64);

    // ================= layer 0 (H=4, D=32) =================
    make_wp<4><<<1, 128>>>(w0ab, as0ab, ad0ab, wpS1, wpD1);
    make_wp<4><<<1, 128>>>(w0ba, as0ba, ad0ba, wpS2, wpD2);

    gemm_bias_128<<<gbA, TB>>>(hA, w0ab, nullptr, t1, NA, 128);  // src transform A->B
    gemm_bias_128<<<gbB, TB>>>(hB, w0ba, nullptr, t2, NB, 128);  // src transform B->A

    node_scores<4><<<wbA, TB>>>(hA, wpS1, as1, NA);  // a_s for AB (A nodes)
    node_scores<4><<<wbB, TB>>>(hB, wpD1, ad1, NB);  // a_d for AB (B nodes)
    node_scores<4><<<wbB, TB>>>(hB, wpS2, as2, NB);  // a_s for BA (B nodes)
    node_scores<4><<<wbA, TB>>>(hA, wpD2, ad2, NA);  // a_d for BA (A nodes)

    gat_aggregate<4><<<wbB, TB>>>(rpAB, srcAB, as1, ad1, t1, nB, NB);
    gat_aggregate<4><<<wbA, TB>>>(rpBA, srcBA, as2, ad2, t2, nA, NA);

    ln_relu_residual<<<wbA, TB>>>(nA, b0ba, g0A, bn0A, hA, hA, NA);
    ln_relu_residual<<<wbB, TB>>>(nB, b0ab, g0B, bn0B, hB, hB, NB);

    // ================= layer 1 (H=1, D=128) =================
    make_wp<1><<<1, 128>>>(w1ab, as1ab, ad1ab, wpS1, wpD1);
    make_wp<1><<<1, 128>>>(w1ba, as1ba, ad1ba, wpS2, wpD2);

    gemm_bias_128<<<gbA, TB>>>(hA, w1ab, nullptr, t1, NA, 128);
    gemm_bias_128<<<gbB, TB>>>(hB, w1ba, nullptr, t2, NB, 128);

    node_scores<1><<<wbA, TB>>>(hA, wpS1, as1, NA);
    node_scores<1><<<wbB, TB>>>(hB, wpD1, ad1, NB);
    node_scores<1><<<wbB, TB>>>(hB, wpS2, as2, NB);
    node_scores<1><<<wbA, TB>>>(hA, wpD2, ad2, NA);

    gat_aggregate<1><<<wbB, TB>>>(rpAB, srcAB, as1, ad1, t1, nB, NB);
    gat_aggregate<1><<<wbA, TB>>>(rpBA, srcBA, as2, ad2, t2, nA, NA);

    float* outA = (float*)d_out;
    float* outB = outA + (size_t)NA * 128;
    ln_relu_residual<<<wbA, TB>>>(nA, b1ba, g1A, bn1A, hA, outA, NA);
    ln_relu_residual<<<wbB, TB>>>(nB, b1ab, g1B, bn1B, hB, outB, NB);
}